// round 17
// baseline (speedup 1.0000x reference)
#include <cuda_runtime.h>
#include <cuda_bf16.h>
#include <cstdint>

// DifferentiableSelector, two-pass L2-resident streaming, 3 CTAs/SM.
//  R13 post-mortem: DRAM traffic is ~75MB (L2 keeps scores warm across graph
//  replays) so the floor is ~12us; the 1-CTA/SM mega-block design was
//  latency-bound on its own reduce/store phases. New shape: 444 persistent
//  CTAs (3 per SM, all 148 SMs), 512 threads, ~40 regs, no smem on the fast
//  path. Pass 1: __ldcg stream -> sigmoid -> sum + raw max (row lands in L2).
//  Reduce (2 barriers). Pass 2: re-read the row (L2-hot, ~57MB working set
//  < 126MB L2), recompute sigmoid (3 ops/elem - cheaper than storing it),
//  scale, store. 3 CTAs/SM fill each other's reduce/store bubbles.
//  sigmoid(z) = 0.5*tanh.approx(z/2)+0.5 (rel_err 1.7e-6 in R11-R14).
//  Identity-damping proof: raw-score max -> ymax bound (+2e-3 margin for the
//  approx); 2*scale*ymax <= 1 => every factor min(2/(1+a+b),1) == 1 exactly
//  -> damping is the identity. Exact chunked slow path retained.

static constexpr int   T_DIM = 32768;
static constexpr int   NT    = 512;
static constexpr int   F4    = T_DIM / 4 / NT;   // 16 float4 per thread
static constexpr int   MAXG  = 444;              // 3 CTAs x 148 SMs
static constexpr float K_SEL = 64.0f;

// slow path: 8 chunks of 4096 elems, halo 10 (stage 12 = 3 float4)
static constexpr int CHUNK_E = 4096;
static constexpr int CPT     = CHUNK_E / NT;     // 8 contiguous elems/thread

__device__ __forceinline__ float tanh_approx(float x) {
    float r; asm("tanh.approx.f32 %0, %1;" : "=f"(r) : "f"(x)); return r;
}
// sigmoid(x/temp) = 0.5*tanh(x*ch)+0.5, ch = 0.5/temp.
__device__ __forceinline__ float sigt(float x, float ch) {
    return fmaf(0.5f, tanh_approx(x * ch), 0.5f);
}

__global__ __launch_bounds__(NT, 3)
void selector_2pass(const float* __restrict__ scores,
                    const float* __restrict__ log_temp,
                    float* __restrict__ out, int B, int grid)
{
    __shared__ float reds[NT / 32], redm[NT / 32];
    __shared__ float s_scale;
    __shared__ int   s_fast;
    __shared__ __align__(16) float ys[CHUNK_E + 12];   // slow path only

    const int tid = threadIdx.x;

    float temp = __expf(log_temp[0]);
    temp = fminf(fmaxf(temp, 0.1f), 10.0f);
    const float ch = __fdividef(0.5f, temp);

    for (int r = blockIdx.x; r < B; r += grid) {
        const float4* src4 = reinterpret_cast<const float4*>(scores) + (size_t)r * (T_DIM / 4);
        float4*       dst4 = reinterpret_cast<float4*>(out)          + (size_t)r * (T_DIM / 4);

        // ---- pass 1: stream row, sum + raw max (fills L2) ----
        float s0 = 0.f, s1 = 0.f, s2 = 0.f, s3 = 0.f;
        float mxx = -3.4e38f;
#pragma unroll
        for (int k = 0; k < F4; k += 4) {
            float4 a = __ldcg(src4 + tid + (k + 0) * NT);
            float4 b = __ldcg(src4 + tid + (k + 1) * NT);
            float4 c = __ldcg(src4 + tid + (k + 2) * NT);
            float4 d = __ldcg(src4 + tid + (k + 3) * NT);
            mxx = fmaxf(mxx, fmaxf(fmaxf(a.x, a.y), fmaxf(a.z, a.w)));
            mxx = fmaxf(mxx, fmaxf(fmaxf(b.x, b.y), fmaxf(b.z, b.w)));
            mxx = fmaxf(mxx, fmaxf(fmaxf(c.x, c.y), fmaxf(c.z, c.w)));
            mxx = fmaxf(mxx, fmaxf(fmaxf(d.x, d.y), fmaxf(d.z, d.w)));
            s0 += sigt(a.x, ch); s1 += sigt(a.y, ch);
            s2 += sigt(a.z, ch); s3 += sigt(a.w, ch);
            s0 += sigt(b.x, ch); s1 += sigt(b.y, ch);
            s2 += sigt(b.z, ch); s3 += sigt(b.w, ch);
            s0 += sigt(c.x, ch); s1 += sigt(c.y, ch);
            s2 += sigt(c.z, ch); s3 += sigt(c.w, ch);
            s0 += sigt(d.x, ch); s1 += sigt(d.y, ch);
            s2 += sigt(d.z, ch); s3 += sigt(d.w, ch);
        }
        float sum = (s0 + s1) + (s2 + s3);

        // ---- reduce: sum (budget) + raw max (identity proof) ----
#pragma unroll
        for (int o = 16; o > 0; o >>= 1) {
            sum += __shfl_xor_sync(0xffffffffu, sum, o);
            mxx = fmaxf(mxx, __shfl_xor_sync(0xffffffffu, mxx, o));
        }
        if ((tid & 31) == 0) { reds[tid >> 5] = sum; redm[tid >> 5] = mxx; }
        __syncthreads();
        if (tid < 32) {
            float s = (tid < NT / 32) ? reds[tid] : 0.0f;
            float m = (tid < NT / 32) ? redm[tid] : -3.4e38f;
#pragma unroll
            for (int o = 8; o > 0; o >>= 1) {
                s += __shfl_xor_sync(0xffffffffu, s, o);
                m = fmaxf(m, __shfl_xor_sync(0xffffffffu, m, o));
            }
            if (tid == 0) {
                const float bb    = fmaxf(s, 1e-6f);
                const float scale = fminf(K_SEL / bb, 1.0f);
                const float ymax_b = sigt(m, ch) + 2e-3f;   // approx margin
                s_scale = scale;
                s_fast  = (2.0f * scale * ymax_b <= 1.0f) ? 1 : 0;
            }
        }
        __syncthreads();
        const float scale = s_scale;

        if (s_fast) {
            // ---- pass 2 (fast): re-read L2-hot row, sigmoid, scale, store ----
#pragma unroll
            for (int k = 0; k < F4; k += 4) {
                float4 a = __ldcg(src4 + tid + (k + 0) * NT);
                float4 b = __ldcg(src4 + tid + (k + 1) * NT);
                float4 c = __ldcg(src4 + tid + (k + 2) * NT);
                float4 d = __ldcg(src4 + tid + (k + 3) * NT);
                a.x = sigt(a.x, ch) * scale; a.y = sigt(a.y, ch) * scale;
                a.z = sigt(a.z, ch) * scale; a.w = sigt(a.w, ch) * scale;
                b.x = sigt(b.x, ch) * scale; b.y = sigt(b.y, ch) * scale;
                b.z = sigt(b.z, ch) * scale; b.w = sigt(b.w, ch) * scale;
                c.x = sigt(c.x, ch) * scale; c.y = sigt(c.y, ch) * scale;
                c.z = sigt(c.z, ch) * scale; c.w = sigt(c.w, ch) * scale;
                d.x = sigt(d.x, ch) * scale; d.y = sigt(d.y, ch) * scale;
                d.z = sigt(d.z, ch) * scale; d.w = sigt(d.w, ch) * scale;
                if (k == 0 && tid == 0) a.x = 0.0f;        // y[row][0] = 0
                __stcs(dst4 + tid + (k + 0) * NT, a);
                __stcs(dst4 + tid + (k + 1) * NT, b);
                __stcs(dst4 + tid + (k + 2) * NT, c);
                __stcs(dst4 + tid + (k + 3) * NT, d);
            }
        } else {
            // ---- SLOW PATH (exact): 8 chunks of 4096, smem staging ----
            float* dst = reinterpret_cast<float*>(dst4);
            for (int c = 0; c < T_DIM / CHUNK_E; ++c) {
                // stage y for chunk c + 12-elem halo (recompute from L2-hot x)
                float4* ys4 = reinterpret_cast<float4*>(ys);
                {
                    float4 a = __ldcg(src4 + c * (CHUNK_E / 4) + tid);
                    float4 b = __ldcg(src4 + c * (CHUNK_E / 4) + NT + tid);
                    a.x = sigt(a.x, ch) * scale; a.y = sigt(a.y, ch) * scale;
                    a.z = sigt(a.z, ch) * scale; a.w = sigt(a.w, ch) * scale;
                    b.x = sigt(b.x, ch) * scale; b.y = sigt(b.y, ch) * scale;
                    b.z = sigt(b.z, ch) * scale; b.w = sigt(b.w, ch) * scale;
                    ys4[tid]      = a;
                    ys4[NT + tid] = b;
                    if (tid < 3) {   // halo wraps within the row (jnp.roll)
                        int gf = (c * (CHUNK_E / 4) + 2 * NT + tid) & (T_DIM / 4 - 1);
                        float4 h = __ldcg(src4 + gf);
                        h.x = sigt(h.x, ch) * scale; h.y = sigt(h.y, ch) * scale;
                        h.z = sigt(h.z, ch) * scale; h.w = sigt(h.w, ch) * scale;
                        ys4[2 * NT + tid] = h;
                    }
                }
                __syncthreads();

                float a[CPT + 10];
                const int st = CPT * tid;
#pragma unroll
                for (int j = 0; j < CPT + 10; ++j) a[j] = ys[st + j];
#pragma unroll
                for (int j = 0; j < CPT + 9; ++j) {      // d=1
                    const float t = a[j] + a[j + 1];
                    a[j] *= fminf(__fdividef(2.0f, 1.0f + t), 1.0f);
                }
#pragma unroll
                for (int j = 0; j < CPT + 7; ++j) {      // d=2
                    const float t = a[j] + a[j + 2];
                    a[j] *= fminf(__fdividef(2.0f, 1.0f + t), 1.0f);
                }
#pragma unroll
                for (int j = 0; j < CPT + 4; ++j) {      // d=3
                    const float t = a[j] + a[j + 3];
                    a[j] *= fminf(__fdividef(2.0f, 1.0f + t), 1.0f);
                }
#pragma unroll
                for (int j = 0; j < CPT; ++j) {          // d=4
                    const float t = a[j] + a[j + 4];
                    a[j] *= fminf(__fdividef(2.0f, 1.0f + t), 1.0f);
                }
                if (c == 0 && tid == 0) a[0] = 0.0f;     // y[row][0] = 0
#pragma unroll
                for (int j = 0; j < CPT; ++j) dst[c * CHUNK_E + st + j] = a[j];
                __syncthreads();
            }
        }
    }
}

extern "C" void kernel_launch(void* const* d_in, const int* in_sizes, int n_in,
                              void* d_out, int out_size)
{
    // metadata order: scores [B,T] fp32, log_temperature scalar fp32 (pick by size)
    const float* scores;
    const float* log_temp;
    int n_scores;
    if (in_sizes[0] > in_sizes[1]) {
        scores = (const float*)d_in[0]; log_temp = (const float*)d_in[1];
        n_scores = in_sizes[0];
    } else {
        scores = (const float*)d_in[1]; log_temp = (const float*)d_in[0];
        n_scores = in_sizes[1];
    }
    const int B = n_scores / T_DIM;               // 512
    const int grid = (B < MAXG) ? B : MAXG;       // 444 persistent CTAs

    selector_2pass<<<grid, NT>>>(scores, log_temp, (float*)d_out, B, grid);
}